// round 12
// baseline (speedup 1.0000x reference)
#include <cuda_runtime.h>

// Reverse cummax along axis 1 of [B=16, H=128, W=128, C=256] float32.
// out[b,h,w,c] = max over h' >= h of in[b,h',w,c].
//
// R12: R9 dataflow (interleaved prefetch ring D=8, __ldcs reads, immediate
// offsets, 2048x64 launch — best profile: DRAM 76.2%, 80.4us) with ONE
// change: stores use st.global.wt (write-through). Store-policy sweep so far:
//   __stcs (evict-first): DRAM 76.2%   default (write-back): DRAM 74.0%
// Write-through removes output dirty-line residency from L2 entirely and
// hands the HBM controller a steady early store stream.

#define B 16
#define H 128
#define HS 8192               // h-stride in float4 (W*C/4)
#define NCOLS (B * HS)        // 131072 columns
#define D 8                   // ring depth
#define NCHUNK (H / D)        // 16

__device__ __forceinline__ float4 fmax4(float4 a, float4 b) {
    float4 r;
    r.x = fmaxf(a.x, b.x);
    r.y = fmaxf(a.y, b.y);
    r.z = fmaxf(a.z, b.z);
    r.w = fmaxf(a.w, b.w);
    return r;
}

__device__ __forceinline__ void stwt4(float4* p, float4 v) {
    asm volatile("st.global.wt.v4.f32 [%0], {%1, %2, %3, %4};"
                 :: "l"(p), "f"(v.x), "f"(v.y), "f"(v.z), "f"(v.w)
                 : "memory");
}

__global__ __launch_bounds__(64) void revcummax_kernel(
    const float4* __restrict__ in, float4* __restrict__ out) {
    int idx = blockIdx.x * blockDim.x + threadIdx.x;

    int b = idx >> 13;           // / HS
    int inner = idx & (HS - 1);
    long long base = (long long)b * H * (long long)HS + inner;

    // Cursors point at the TOP of the current chunk (highest h of the chunk).
    const float4* pl = in + base + (H - 1) * (long long)HS;
    float4* q = out + base + (H - 1) * (long long)HS;

    // Prologue: fill the ring with h = H-1 .. H-D (immediate offsets).
    float4 v[D];
#pragma unroll
    for (int i = 0; i < D; i++)
        v[i] = __ldcs(pl - (long long)i * HS);
    pl -= (long long)D * HS;

    float4 m;
    m.x = m.y = m.z = m.w = -__int_as_float(0x7f800000);  // -inf

    // Steady state: 15 chunks. Consume slot i, immediately prefetch the same
    // slot from the next chunk (constant offset from pl), max, store.
#pragma unroll 1
    for (int c = 0; c < NCHUNK - 1; c++) {
#pragma unroll
        for (int i = 0; i < D; i++) {
            float4 x = v[i];
            v[i] = __ldcs(pl - (long long)i * HS);
            m = fmax4(m, x);
            stwt4(q - (long long)i * HS, m);
        }
        pl -= (long long)D * HS;
        q -= (long long)D * HS;
    }

    // Drain: last chunk (h = D-1 .. 0), stores only.
#pragma unroll
    for (int i = 0; i < D; i++) {
        m = fmax4(m, v[i]);
        stwt4(q - (long long)i * HS, m);
    }
}

extern "C" void kernel_launch(void* const* d_in, const int* in_sizes, int n_in,
                              void* d_out, int out_size) {
    const float4* in = (const float4*)d_in[0];
    float4* out = (float4*)d_out;
    int threads = 64;
    int blocks = NCOLS / threads;  // 2048
    revcummax_kernel<<<blocks, threads>>>(in, out);
}